// round 16
// baseline (speedup 1.0000x reference)
#include <cuda_runtime.h>
#include <math.h>
#include <stdint.h>

#define CK_B   4
#define CK_S   1024
#define CK_HID 768
#define CK_H   6
#define CK_D   64
#define CK_AH  384
#define CK_KS  9
#define CK_BS  (CK_B*CK_S)

// ---------------- scratch (device globals; no allocation allowed) ----------
__device__ float g_mq [CK_BS*CK_AH];
__device__ float g_mk [CK_BS*CK_AH];
__device__ float g_mv [CK_BS*CK_AH];
__device__ float g_mkc[CK_BS*CK_AH];
__device__ float g_co [CK_BS*CK_AH];
__device__ float g_dw [CK_BS*CK_HID];
__device__ float g_pwT[CK_HID*CK_AH];
__device__ float g_ckl0[CK_BS*64];
__device__ float g_ckl1[CK_BS*64];
__device__ float g_ckl2[CK_BS*64];
__device__ float g_cko[CK_BS*CK_H*CK_KS];
__device__ float g_tds[CK_BS];

// ---------------- tf32 helpers ---------------------------------------------
__device__ __forceinline__ uint32_t f2tf32(float f) {
    uint32_t u;
    asm("cvt.rna.tf32.f32 %0, %1;" : "=r"(u) : "f"(f));
    return u;
}
__device__ __forceinline__ uint4 cvt4(float4 v) {
    return make_uint4(f2tf32(v.x), f2tf32(v.y), f2tf32(v.z), f2tf32(v.w));
}
__device__ __forceinline__ void mma_tf32(float c[4], const uint32_t a[4],
                                         const uint32_t b[2]) {
    asm volatile(
        "mma.sync.aligned.m16n8k8.row.col.f32.tf32.tf32.f32 "
        "{%0,%1,%2,%3}, {%4,%5,%6,%7}, {%8,%9}, {%0,%1,%2,%3};"
        : "+f"(c[0]), "+f"(c[1]), "+f"(c[2]), "+f"(c[3])
        : "r"(a[0]), "r"(a[1]), "r"(a[2]), "r"(a[3]), "r"(b[0]), "r"(b[1]));
}

// ---------------- batched TF32 tensor-core GEMM (reg-prefetch) --------------
__global__ __launch_bounds__(256, 2) void gemm5_tf32(
    const float* __restrict__ Q, const float* __restrict__ Kin,
    const float* __restrict__ V, const float* __restrict__ dw,
    const float* __restrict__ Wq, const float* __restrict__ Wk,
    const float* __restrict__ Wv, const float* __restrict__ coW,
    const float* __restrict__ pwT,
    const float* __restrict__ cob, const float* __restrict__ sepb,
    float* __restrict__ mq, float* __restrict__ mk, float* __restrict__ mv,
    float* __restrict__ co, float* __restrict__ mkc)
{
    const float *A, *B, *bias; float* C;
    switch (blockIdx.z) {
        case 0:  A = Q;   B = Wq;  bias = nullptr; C = mq;  break;
        case 1:  A = Kin; B = Wk;  bias = nullptr; C = mk;  break;
        case 2:  A = V;   B = Wv;  bias = nullptr; C = mv;  break;
        case 3:  A = V;   B = coW; bias = cob;     C = co;  break;
        default: A = dw;  B = pwT; bias = sepb;    C = mkc; break;
    }
    __shared__ uint32_t As[128][36];
    __shared__ uint32_t Bs[32][132];

    int tid  = threadIdx.x;
    int m0   = blockIdx.y * 128;
    int n0   = blockIdx.x * 128;
    int lane = tid & 31;
    int g    = lane >> 2;
    int t    = lane & 3;
    int warp = tid >> 5;
    int wm   = warp >> 1;
    int wn   = warp & 1;

    float c[2][8][4];
    #pragma unroll
    for (int i = 0; i < 2; i++)
        #pragma unroll
        for (int j = 0; j < 8; j++)
            #pragma unroll
            for (int r = 0; r < 4; r++) c[i][j][r] = 0.0f;

    float4 pa[4], pb[4];
    #pragma unroll
    for (int i = 0; i < 4; i++) {
        int e = tid + i * 256;
        int row = e >> 3, kq = (e & 7) << 2;
        pa[i] = *(const float4*)&A[(size_t)(m0 + row) * CK_HID + kq];
        int kr = e >> 5, nq = (e & 31) << 2;
        pb[i] = *(const float4*)&B[(size_t)kr * CK_AH + n0 + nq];
    }

    for (int k0 = 0; k0 < CK_HID; k0 += 32) {
        __syncthreads();
        #pragma unroll
        for (int i = 0; i < 4; i++) {
            int e = tid + i * 256;
            int row = e >> 3, kq = (e & 7) << 2;
            *(uint4*)&As[row][kq] = cvt4(pa[i]);
            int kr = e >> 5, nq = (e & 31) << 2;
            *(uint4*)&Bs[kr][nq] = cvt4(pb[i]);
        }
        __syncthreads();
        if (k0 + 32 < CK_HID) {
            #pragma unroll
            for (int i = 0; i < 4; i++) {
                int e = tid + i * 256;
                int row = e >> 3, kq = (e & 7) << 2;
                pa[i] = *(const float4*)
                    &A[(size_t)(m0 + row) * CK_HID + k0 + 32 + kq];
                int kr = e >> 5, nq = (e & 31) << 2;
                pb[i] = *(const float4*)
                    &B[(size_t)(k0 + 32 + kr) * CK_AH + n0 + nq];
            }
        }
        #pragma unroll
        for (int ks = 0; ks < 4; ks++) {
            int kk = ks * 8;
            uint32_t a[2][4], b[8][2];
            #pragma unroll
            for (int i = 0; i < 2; i++) {
                int bm = wm * 32 + i * 16;
                a[i][0] = As[bm + g    ][kk + t];
                a[i][1] = As[bm + g + 8][kk + t];
                a[i][2] = As[bm + g    ][kk + t + 4];
                a[i][3] = As[bm + g + 8][kk + t + 4];
            }
            #pragma unroll
            for (int j = 0; j < 8; j++) {
                int bn = wn * 64 + j * 8;
                b[j][0] = Bs[kk + t    ][bn + g];
                b[j][1] = Bs[kk + t + 4][bn + g];
            }
            #pragma unroll
            for (int i = 0; i < 2; i++)
                #pragma unroll
                for (int j = 0; j < 8; j++)
                    mma_tf32(c[i][j], a[i], b[j]);
        }
    }
    #pragma unroll
    for (int i = 0; i < 2; i++) {
        int r0 = m0 + wm * 32 + i * 16 + g;
        #pragma unroll
        for (int j = 0; j < 8; j++) {
            int col = n0 + wn * 64 + j * 8 + t * 2;
            float b0 = bias ? bias[col]     : 0.0f;
            float b1 = bias ? bias[col + 1] : 0.0f;
            C[(size_t)r0 * CK_AH + col]           = c[i][j][0] + b0;
            C[(size_t)r0 * CK_AH + col + 1]       = c[i][j][1] + b1;
            C[(size_t)(r0 + 8) * CK_AH + col]     = c[i][j][2] + b0;
            C[(size_t)(r0 + 8) * CK_AH + col + 1] = c[i][j][3] + b1;
        }
    }
}

// ---------------- transpose pw_w (AH,HID) -> (HID,AH) -----------------------
__global__ __launch_bounds__(256) void transpose_pw(
    const float* __restrict__ pw, float* __restrict__ pwT)
{
    int idx = blockIdx.x * 256 + threadIdx.x;
    if (idx >= CK_AH * CK_HID) return;
    int o = idx / CK_HID, c = idx % CK_HID;
    pwT[(size_t)c * CK_AH + o] = pw[idx];
}

// ---------------- depthwise conv (float4 over channels) ---------------------
__global__ __launch_bounds__(256) void dwconv_kernel(
    const float* __restrict__ Kin, const float* __restrict__ dww,
    float* __restrict__ outp)
{
    int idx = blockIdx.x * 256 + threadIdx.x;           // over BS * HID/4
    if (idx >= CK_BS * (CK_HID / 4)) return;
    int c4 = idx % (CK_HID / 4);
    int bs = idx / (CK_HID / 4);
    int s  = bs % CK_S;
    int c  = c4 * 4;
    float w[4][9];
    #pragma unroll
    for (int j = 0; j < 4; j++)
        #pragma unroll
        for (int t = 0; t < 9; t++) w[j][t] = dww[(c + j) * 9 + t];
    float4 acc = make_float4(0.f, 0.f, 0.f, 0.f);
    #pragma unroll
    for (int t = 0; t < 9; t++) {
        int ss = s + t - 4;
        if (ss >= 0 && ss < CK_S) {
            float4 x = *(const float4*)&Kin[((size_t)(bs - s + ss)) * CK_HID + c];
            acc.x += x.x * w[0][t];
            acc.y += x.y * w[1][t];
            acc.z += x.z * w[2][t];
            acc.w += x.w * w[3][t];
        }
    }
    *(float4*)&outp[(size_t)bs * CK_HID + c] = acc;
}

// ---------- ck logits GEMM, k-split in 3 slabs (grid.y) ----------------------
__global__ __launch_bounds__(256) void ckgemm_tf32(
    const float* __restrict__ mq, const float* __restrict__ mkc,
    const float* __restrict__ ckW,
    float* __restrict__ ckl0, float* __restrict__ ckl1,
    float* __restrict__ ckl2)
{
    __shared__ uint32_t As[32][68];
    __shared__ uint32_t Bs[64][72];
    int tid = threadIdx.x;
    int warp = tid >> 5, lane = tid & 31;
    int g = lane >> 2, t = lane & 3;
    int m0 = blockIdx.x * 32;
    int kbase = blockIdx.y * 128;
    float* ckl = (blockIdx.y == 0) ? ckl0 : ((blockIdx.y == 1) ? ckl1 : ckl2);
    int wm = warp & 1, wn = warp >> 1;

    float c[2][4];
    #pragma unroll
    for (int nt = 0; nt < 2; nt++)
        #pragma unroll
        for (int r = 0; r < 4; r++) c[nt][r] = 0.0f;

    for (int kc = 0; kc < 2; kc++) {
        int k0 = kbase + kc * 64;
        __syncthreads();
        #pragma unroll
        for (int i = 0; i < 2; i++) {
            int e4 = tid + i * 256;
            int row = e4 >> 4, d4 = (e4 & 15) << 2;
            float4 a4 = *(const float4*)&mq[(size_t)(m0 + row) * CK_AH + k0 + d4];
            float4 b4 = *(const float4*)&mkc[(size_t)(m0 + row) * CK_AH + k0 + d4];
            uint4 u;
            u.x = f2tf32(a4.x * b4.x); u.y = f2tf32(a4.y * b4.y);
            u.z = f2tf32(a4.z * b4.z); u.w = f2tf32(a4.w * b4.w);
            *(uint4*)&As[row][d4] = u;
        }
        #pragma unroll
        for (int i = 0; i < 18; i++) {
            int e = tid + i * 256;
            int kr = e / 72, o = e - kr * 72;
            float v = (o < 54) ? ckW[(size_t)(k0 + kr) * 54 + o] : 0.0f;
            Bs[kr][o] = f2tf32(v);
        }
        __syncthreads();
        #pragma unroll
        for (int kk = 0; kk < 64; kk += 8) {
            uint32_t a[4];
            int mb = wm * 16;
            a[0] = As[mb + g    ][kk + t];
            a[1] = As[mb + g + 8][kk + t];
            a[2] = As[mb + g    ][kk + t + 4];
            a[3] = As[mb + g + 8][kk + t + 4];
            #pragma unroll
            for (int nt = 0; nt < 2; nt++) {
                uint32_t bb[2];
                int bn = wn * 16 + nt * 8;
                bb[0] = Bs[kk + t    ][bn + g];
                bb[1] = Bs[kk + t + 4][bn + g];
                mma_tf32(c[nt], a, bb);
            }
        }
    }
    int r = m0 + wm * 16 + g;
    #pragma unroll
    for (int nt = 0; nt < 2; nt++) {
        int col = wn * 16 + nt * 8 + t * 2;
        ckl[(size_t)r * 64 + col]           = c[nt][0];
        ckl[(size_t)r * 64 + col + 1]       = c[nt][1];
        ckl[(size_t)(r + 8) * 64 + col]     = c[nt][2];
        ckl[(size_t)(r + 8) * 64 + col + 1] = c[nt][3];
    }
}

// ---------- softmax over KS=9 per (pos, head), summing k-slabs ---------------
__global__ __launch_bounds__(256) void ck_softmax(
    const float* __restrict__ ckl0, const float* __restrict__ ckl1,
    const float* __restrict__ ckl2, const float* __restrict__ ckb,
    float* __restrict__ cko)
{
    int gid = blockIdx.x * 256 + threadIdx.x;
    if (gid >= CK_BS * CK_H) return;
    int p = gid / CK_H, h = gid % CK_H;
    float v[9]; float m = -1e30f;
    #pragma unroll
    for (int k = 0; k < 9; k++) {
        int col = h * 9 + k;
        v[k] = ckl0[(size_t)p * 64 + col] + ckl1[(size_t)p * 64 + col]
             + ckl2[(size_t)p * 64 + col] + ckb[col];
        m = fmaxf(m, v[k]);
    }
    float s = 0.0f;
    #pragma unroll
    for (int k = 0; k < 9; k++) { v[k] = __expf(v[k] - m); s += v[k]; }
    float inv = 1.0f / s;
    #pragma unroll
    for (int k = 0; k < 9; k++)
        cko[(size_t)p * 54 + h * 9 + k] = v[k] * inv;
}

// -------- dynamic-span conv out (float4 over head-dim) ----------------------
__global__ __launch_bounds__(256) void convout_kernel(
    const float* __restrict__ co, const float* __restrict__ cko,
    float* __restrict__ out)
{
    int idx = blockIdx.x * 256 + threadIdx.x;          // over BS * AH/4
    if (idx >= CK_BS * (CK_AH / 4)) return;
    int hd4 = idx % (CK_AH / 4);
    int bs  = idx / (CK_AH / 4);
    int s   = bs % CK_S;
    int hd  = hd4 * 4;
    int h   = hd >> 6;
    const float* ckp = cko + (size_t)bs * 54 + h * 9;
    float ck[9];
    #pragma unroll
    for (int k = 0; k < 9; k++) ck[k] = ckp[k];
    float4 acc = make_float4(0.f, 0.f, 0.f, 0.f);
    #pragma unroll
    for (int k = 0; k < 9; k++) {
        int ss = s + k - 4;
        if (ss >= 0 && ss < CK_S) {
            float4 x = *(const float4*)&co[((size_t)(bs - s + ss)) * CK_AH + hd];
            acc.x += x.x * ck[k];
            acc.y += x.y * ck[k];
            acc.z += x.z * ck[k];
            acc.w += x.w * ck[k];
        }
    }
    *(float4*)&out[(size_t)bs * (2 * CK_AH) + CK_AH + hd] = acc;
}

// ---------------- masked softmax of normalized td (per batch) ---------------
__global__ __launch_bounds__(256) void tdsm_kernel(
    const float* __restrict__ td, const int* __restrict__ mask,
    float* __restrict__ out)
{
    __shared__ float red[256];
    int b = blockIdx.x, tid = threadIdx.x;
    float v[4]; float ss = 0.0f;
    #pragma unroll
    for (int t = 0; t < 4; t++) { v[t] = td[b * CK_S + tid + t * 256]; ss += v[t] * v[t]; }
    red[tid] = ss; __syncthreads();
    for (int s = 128; s > 0; s >>= 1) { if (tid < s) red[tid] += red[tid + s]; __syncthreads(); }
    float denom = fmaxf(sqrtf(red[0]), 1e-12f);
    __syncthreads();
    float x[4]; float m = -1e30f;
    #pragma unroll
    for (int t = 0; t < 4; t++) {
        int j = tid + t * 256;
        x[t] = mask[b * CK_S + j] ? (v[t] / denom) : -1e4f;
        m = fmaxf(m, x[t]);
    }
    red[tid] = m; __syncthreads();
    for (int s = 128; s > 0; s >>= 1) { if (tid < s) red[tid] = fmaxf(red[tid], red[tid + s]); __syncthreads(); }
    m = red[0]; __syncthreads();
    float e[4]; float se = 0.0f;
    #pragma unroll
    for (int t = 0; t < 4; t++) { e[t] = __expf(x[t] - m); se += e[t]; }
    red[tid] = se; __syncthreads();
    for (int s = 128; s > 0; s >>= 1) { if (tid < s) red[tid] += red[tid + s]; __syncthreads(); }
    float inv = 1.0f / red[0];
    #pragma unroll
    for (int t = 0; t < 4; t++) out[b * CK_S + tid + t * 256] = e[t] * inv;
}

// ---------------- fused attention: pipelined, spill-free --------------------
// 32 rows/CTA, 512 threads, 1 CTA/SM (128-reg cap). Phase 2/3 carries NO
// per-element register array: the cumsum pass recomputes exp on the fly and
// overwrites scores in smem, keeping regs ~40 -> no local-memory spills.
// Phases 1 & 4 double-buffer chunks with ONE barrier per iteration.
#define ATTN_SCP  1044   // 1044 % 32 == 20
#define ATTN_KP1  68     // phase-1 pitch (a-frag bank 4g+t)
#define ATTN_KP4  72     // phase-4 pitch (b-frag bank 8t+g)
#define ATTN_QSP  40     // q pitch: bank 8t+g distinct
#define ATTN_KVW  (2*64*72)  // double buffer, max pitch
#define ATTN_ROWS 32
#define ATTN_THR  512
#define ATTN_SMEM_WORDS (ATTN_ROWS*ATTN_SCP + ATTN_KVW + 64*ATTN_QSP + 1040 + 264)
#define ATTN_SMEM_BYTES (ATTN_SMEM_WORDS*4)
#define LOG2E 1.4426950408889634f

__global__ __launch_bounds__(ATTN_THR, 1) void attn_kernel(
    const float* __restrict__ mq, const float* __restrict__ mk,
    const float* __restrict__ mv, const int* __restrict__ mask,
    const float* __restrict__ tdsm, const float* __restrict__ gammas,
    float* __restrict__ out)
{
    extern __shared__ float smem[];
    float*    sc  = smem;                                      // [32][1044]
    uint32_t* kvb = (uint32_t*)(smem + ATTN_ROWS * ATTN_SCP);  // 2 chunk bufs
    uint32_t* qsu = kvb + ATTN_KVW;                            // q tf32 [d][i]
    float*    tds = (float*)(qsu + 64 * ATTN_QSP);             // [1040]
    uint8_t*  amf = (uint8_t*)(tds + 1040);                    // [1040] bytes

    int tid  = threadIdx.x;
    int warp = tid >> 5, lane = tid & 31;
    int g = lane >> 2, t = lane & 3;
    int blk = blockIdx.x;
    int it  = blk & 31;
    int h   = (blk >> 5) % CK_H;
    int b   = blk / (32 * CK_H);
    int i0  = it * ATTN_ROWS;

    int ldj0 = tid >> 4,                ldd0 = (tid & 15) << 2;
    int ldj1 = (tid + ATTN_THR) >> 4,   ldd1 = ((tid + ATTN_THR) & 15) << 2;
    const float* mkbase = mk + (size_t)(b * CK_S) * CK_AH + h * CK_D;
    const float* mvbase = mv + (size_t)(b * CK_S) * CK_AH + h * CK_D;

    for (int e = tid; e < ATTN_ROWS * 64; e += ATTN_THR) {
        int r = e >> 6, d = e & 63;
        qsu[d * ATTN_QSP + r] = f2tf32(
            mq[((size_t)(b * CK_S + i0 + r)) * CK_AH + h * CK_D + d] * 0.125f);
    }
    for (int j = tid; j < CK_S; j += ATTN_THR) {
        int fj = j + (j >> 6);
        amf[fj] = (uint8_t)(mask[b * CK_S + j] ? 1 : 0);
        tds[fj] = tdsm[b * CK_S + j];
    }
    float gamma = -log1pf(expf(gammas[h]));

    float4 r0 = *(const float4*)&mkbase[(size_t)ldj0 * CK_AH + ldd0];
    float4 r1 = *(const float4*)&mkbase[(size_t)ldj1 * CK_AH + ldd1];
    __syncthreads();

    // ---- phase 1: scores^T = K @ q^T, pipelined ----------------------------
    {
        int jb  = (warp & 3) * 16;
        int n0q = (warp >> 2) * 8;
        uint32_t bq[8][2];
        #pragma unroll
        for (int ks = 0; ks < 8; ks++) {
            int kk = ks * 8;
            bq[ks][0] = qsu[(kk + t    ) * ATTN_QSP + n0q + g];
            bq[ks][1] = qsu[(kk + t + 4) * ATTN_QSP + n0q + g];
        }
        #pragma unroll 1
        for (int ci = 0; ci < 16; ci++) {
            uint32_t* cb = kvb + (ci & 1) * (64 * ATTN_KP1);
            *(uint4*)&cb[ldj0 * ATTN_KP1 + ldd0] = cvt4(r0);
            *(uint4*)&cb[ldj1 * ATTN_KP1 + ldd1] = cvt4(r1);
            __syncthreads();
            if (ci < 15) {
                const float* nb = mkbase + (size_t)(ci + 1) * 64 * CK_AH;
                r0 = *(const float4*)&nb[(size_t)ldj0 * CK_AH + ldd0];
                r1 = *(const float4*)&nb[(size_t)ldj1 * CK_AH + ldd1];
            }
            float c[4] = {0.f, 0.f, 0.f, 0.f};
            #pragma unroll
            for (int ks = 0; ks < 8; ks++) {
                int kk = ks * 8;
                uint32_t a[4];
                a[0] = cb[(jb + g    ) * ATTN_KP1 + kk + t];
                a[1] = cb[(jb + g + 8) * ATTN_KP1 + kk + t];
                a[2] = cb[(jb + g    ) * ATTN_KP1 + kk + t + 4];
                a[3] = cb[(jb + g + 8) * ATTN_KP1 + kk + t + 4];
                mma_tf32(c, a, bq[ks]);
            }
            int c0 = ci * 64;
            #pragma unroll
            for (int half = 0; half < 2; half++) {
                int jglob = c0 + jb + g + 8 * half;
                int fj = jglob + (jglob >> 6);
                bool on = amf[fj] != 0;
                #pragma unroll
                for (int e = 0; e < 2; e++) {
                    float val = on ? c[2 * half + e] : -1e8f;
                    sc[(n0q + t * 2 + e) * ATTN_SCP + fj] = val;
                }
            }
        }
    }
    __syncthreads();

    // ---- phase 2+3: spill-free softmax/cumsum/effect -----------------------
    {
        int r = tid >> 4;                 // row 0..31
        int l = tid & 15;                 // 64-wide segment
        unsigned ln  = tid & 31;
        unsigned sub = ln & 15;
        float* scr = sc + r * ATTN_SCP + l * 65;
        const float* tdsl = tds + l * 65;
        int irow = i0 + r;

        // pass A: segment exp-sum only (no per-element storage)
        float cum = 0.0f;
        #pragma unroll
        for (int k = 0; k < 64; k++)
            cum += __expf(scr[k]);        // masked (-1e8) underflows to 0
        float x = cum;
        #pragma unroll
        for (int dl = 1; dl < 16; dl <<= 1) {
            float v = __shfl_up_sync(0xffffffffu, x, dl);
            if (sub >= (unsigned)dl) x += v;
        }
        float excl = x - cum;
        float tot  = __shfl_sync(0xffffffffu, x, (ln & 16) | 15);
        float inv  = 1.0f / tot;
        float rem0 = tot - excl;
        float ig2  = inv * gamma * gamma * (LOG2E * LOG2E);
        float posbase = (float)(l * 64 - irow);

        // pass B: recompute exp, running cumsum, effect, overwrite scr with p2
        float s2 = 0.0f;
        float c2 = 0.0f;
        #pragma unroll
        for (int k = 0; k < 64; k++) {
            float sck = scr[k];
            float p = __expf(sck);
            c2 += p;
            float rem = rem0 - c2;
            float pj  = posbase + (float)k;           // j - irow exactly
            float t1  = fmaxf(rem * fabsf(pj), 0.0f);
            float e2  = exp2f(-sqrtf(t1 * ig2));
            float eff = fmaxf(e2, 1e-5f);
            if (pj < 0.0f) eff -= tdsl[k];
            float p2 = __expf(sck * eff);
            s2 += p2;
            scr[k] = p2;
        }
        #pragma unroll
        for (int dl = 8; dl >= 1; dl >>= 1)
            s2 += __shfl_xor_sync(0xffffffffu, s2, dl);
        float inv2 = 1.0f / s2;

        // pass C: normalize in smem, store as tf32 bit pattern
        #pragma unroll
        for (int k = 0; k < 64; k++)
            scr[k] = __uint_as_float(f2tf32(scr[k] * inv2));
    }

    // prefetch V chunk 0 (registers only; ordered vs smem by phase-4 sync)
    r0 = *(const float4*)&mvbase[(size_t)ldj0 * CK_AH + ldd0];
    r1 = *(const float4*)&mvbase[(size_t)ldj1 * CK_AH + ldd1];

    // ---- phase 4: ctx = P @ V, pipelined, ONE barrier per chunk ------------
    {
        int mt = warp & 1;
        int n0 = (warp >> 1) * 8;
        int mb = mt * 16;
        const uint32_t* scu = (const uint32_t*)sc;
        float c[4] = {0.f, 0.f, 0.f, 0.f};
        #pragma unroll 1
        for (int ci = 0; ci < 16; ci++) {
            uint32_t* cb = kvb + (ci & 1) * (64 * ATTN_KP4);
            // STS(ci) -> buf(ci&1): last readers were MMA(ci-2), fenced by
            // sync(ci-1). sync(0) also orders phase-2/3 prob stores.
            *(uint4*)&cb[ldj0 * ATTN_KP4 + ldd0] = cvt4(r0);
            *(uint4*)&cb[ldj1 * ATTN_KP4 + ldd1] = cvt4(r1);
            __syncthreads();
            if (ci < 15) {
                const float* nb = mvbase + (size_t)(ci + 1) * 64 * CK_AH;
                r0 = *(const float4*)&nb[(size_t)ldj0 * CK_AH + ldd0];
                r1 = *(const float4*)&nb[(size_t)ldj1 * CK_AH + ldd1];
            }
            int cbase = ci * 64 + ci;     // c0 + c0/64
            #pragma unroll
            for (int kk = 0; kk < 64; kk += 8) {
                uint32_t a[4], bh[2];
                int f0 = cbase + kk + t, f1 = f0 + 4;
                a[0] = scu[(mb + g    ) * ATTN_SCP + f0];
                a[1] = scu[(mb + g + 8) * ATTN_SCP + f0];
                a[2] = scu[(mb + g    ) * ATTN_SCP + f1];
                a[3] = scu[(mb + g + 8) * ATTN_SCP + f1];
                bh[0] = cb[(kk + t    ) * ATTN_KP4 + n0 + g];
                bh[1] = cb[(kk + t + 4) * ATTN_KP4 + n0 + g];
                mma_tf32(c, a, bh);
            }
        }
        #pragma unroll
        for (int half = 0; half < 2; half++) {
            int r = i0 + mb + g + 8 * half;
            float* op = out + ((size_t)(b * CK_S + r)) * (2 * CK_AH)
                            + h * CK_D + n0 + t * 2;
            op[0] = c[2 * half + 0];
            op[1] = c[2 * half + 1];
        }
    }
}

// ---------------------------------------------------------------------------
extern "C" void kernel_launch(void* const* d_in, const int* in_sizes, int n_in,
                              void* d_out, int out_size)
{
    const float* Q    = (const float*)d_in[0];
    const float* K    = (const float*)d_in[1];
    const float* V    = (const float*)d_in[2];
    const float* td   = (const float*)d_in[3];
    const int*   mask = (const int*)  d_in[4];
    const float* Wq   = (const float*)d_in[5];
    const float* Wk   = (const float*)d_in[6];
    const float* Wv   = (const float*)d_in[7];
    const float* dww  = (const float*)d_in[8];
    const float* pww  = (const float*)d_in[9];
    const float* sepb = (const float*)d_in[10];
    const float* ckW  = (const float*)d_in[11];
    const float* ckb  = (const float*)d_in[12];
    const float* coW  = (const float*)d_in[13];
    const float* cob  = (const float*)d_in[14];
    const float* gam  = (const float*)d_in[15];
    float* out = (float*)d_out;

    float *mq, *mk, *mv, *mkc, *co, *dw, *pwT, *ckl0, *ckl1, *ckl2, *cko, *tds;
    cudaGetSymbolAddress((void**)&mq,   g_mq);
    cudaGetSymbolAddress((void**)&mk,   g_mk);
    cudaGetSymbolAddress((void**)&mv,   g_mv);
    cudaGetSymbolAddress((void**)&mkc,  g_mkc);
    cudaGetSymbolAddress((void**)&co,   g_co);
    cudaGetSymbolAddress((void**)&dw,   g_dw);
    cudaGetSymbolAddress((void**)&pwT,  g_pwT);
    cudaGetSymbolAddress((void**)&ckl0, g_ckl0);
    cudaGetSymbolAddress((void**)&ckl1, g_ckl1);
    cudaGetSymbolAddress((void**)&ckl2, g_ckl2);
    cudaGetSymbolAddress((void**)&cko,  g_cko);
    cudaGetSymbolAddress((void**)&tds,  g_tds);

    transpose_pw<<<(CK_AH * CK_HID + 255) / 256, 256>>>(pww, pwT);
    dwconv_kernel<<<(CK_BS * (CK_HID / 4) + 255) / 256, 256>>>(K, dww, dw);

    dim3 ggrid(CK_AH / 128, CK_BS / 128, 5);
    gemm5_tf32<<<ggrid, 256>>>(Q, K, V, dw, Wq, Wk, Wv, coW, pwT,
                               cob, sepb, mq, mk, mv, co, mkc);

    dim3 ckgrid(CK_BS / 32, 3);
    ckgemm_tf32<<<ckgrid, 256>>>(mq, mkc, ckW, ckl0, ckl1, ckl2);
    ck_softmax<<<(CK_BS * CK_H + 255) / 256, 256>>>(ckl0, ckl1, ckl2, ckb, cko);
    convout_kernel<<<(CK_BS * (CK_AH / 4) + 255) / 256, 256>>>(co, cko, out);
    tdsm_kernel<<<CK_B, 256>>>(td, mask, tds);

    cudaFuncSetAttribute(attn_kernel, cudaFuncAttributeMaxDynamicSharedMemorySize,
                         ATTN_SMEM_BYTES);
    attn_kernel<<<CK_B * CK_H * (CK_S / ATTN_ROWS), ATTN_THR, ATTN_SMEM_BYTES>>>(
        mq, mk, mv, mask, tds, gam, out);
}